// round 4
// baseline (speedup 1.0000x reference)
#include <cuda_runtime.h>
#include <cuda_fp16.h>
#include <cstdint>

#define GRID_H 1024
#define GRID_W 1024
#define DIM_FEAT 32
#define HW (GRID_H * GRID_W)

// 64 MB static scratch: params transposed to [H, W, C] fp16. Each pixel's 32
// channels = contiguous 64B; two x-adjacent pixels = contiguous 128B span.
// Whole table fits L2 (126MB).
__device__ __half g_params_t[(size_t)DIM_FEAT * HW];

// ---------------------------------------------------------------------------
// Transpose [C, H*W] fp32 -> [H*W, C] fp16. Reads coalesced 128B/warp;
// writes vectorized as half2 -> 128B/warp.
// ---------------------------------------------------------------------------
__global__ void transpose_kernel(const float* __restrict__ p,
                                 __half* __restrict__ pt) {
    __shared__ float tile[32][33];  // +1 pad
    const int pix0 = blockIdx.x * 32;
    const int tx = threadIdx.x;     // 0..31
    const int ty = threadIdx.y;     // 0..7
    const int l = ty * 32 + tx;     // 0..255

    // Read: channel-major rows, W-contiguous -> coalesced.
#pragma unroll
    for (int i = 0; i < 32; i += 8) {
        tile[ty + i][tx] = __ldcs(&p[(size_t)(ty + i) * HW + pix0 + tx]);
    }
    __syncthreads();

    // Write: 256 threads cover 16 pixels/iter; thread writes one half2
    // (two channels of one pixel). 2 iters for 32 pixels.
    __half2* ptv = (__half2*)pt;
#pragma unroll
    for (int it = 0; it < 2; it++) {
        const int pix = it * 16 + (l >> 4);       // 0..31 within block
        const int c2 = l & 15;                    // channel pair 0..15
        const float a = tile[2 * c2 + 0][pix];
        const float b = tile[2 * c2 + 1][pix];
        ptv[(size_t)(pix0 + pix) * (DIM_FEAT / 2) + c2] =
            __floats2half2_rn(a, b);
    }
}

// ---------------------------------------------------------------------------
// Bilinear sample: 8 lanes per point.
// Base pixel clamped to <= W-2 / H-2 (fx/fy shift to 1.0 at the border,
// which is the identical interpolation), so each row's two x-corners are one
// contiguous 128B span: lanes 0-3 = left pixel chunks, lanes 4-7 = right.
// Two span loads (row0,row1), x-combine via shfl_xor(4), one full-width
// 128B/point streaming store.
// ---------------------------------------------------------------------------
__global__ void sample_kernel(const float2* __restrict__ coord,
                              const __half* __restrict__ pt,
                              float* __restrict__ out, int n) {
    const int t = blockIdx.x * blockDim.x + threadIdx.x;
    const int pidx = t >> 3;     // point index
    const int l8 = t & 7;        // lane within point
    if (pidx >= n) return;

    const float2 xy = __ldcs(&coord[pidx]);

    // align_corners=True mapping
    const float ix = (xy.x + 1.0f) * 0.5f * (float)(GRID_W - 1);
    const float iy = (xy.y + 1.0f) * 0.5f * (float)(GRID_H - 1);

    int bx = (int)floorf(ix);
    int by = (int)floorf(iy);
    bx = min(max(bx, 0), GRID_W - 2);
    by = min(max(by, 0), GRID_H - 2);
    const float fx = ix - (float)bx;   // in [0,1]; ==1 at right border
    const float fy = iy - (float)by;

    // This lane covers left (l8<4) or right (l8>=4) corner.
    const float wx = (l8 < 4) ? (1.0f - fx) : fx;
    const float w0 = wx * (1.0f - fy);
    const float w1 = wx * fy;

    // 128B span [pixel(by,bx), pixel(by,bx+1)] split into 8 x 16B chunks.
    const size_t base0 = ((size_t)by * GRID_W + bx) * DIM_FEAT + (size_t)l8 * 8;
    const uint4 r0 = *(const uint4*)(pt + base0);
    const uint4 r1 = *(const uint4*)(pt + base0 + (size_t)GRID_W * DIM_FEAT);

    float acc[8];
    {
        const unsigned u0[4] = {r0.x, r0.y, r0.z, r0.w};
        const unsigned u1[4] = {r1.x, r1.y, r1.z, r1.w};
#pragma unroll
        for (int j = 0; j < 4; j++) {
            const float2 a = __half22float2(*(const __half2*)&u0[j]);
            const float2 b = __half22float2(*(const __half2*)&u1[j]);
            acc[2 * j + 0] = fmaf(a.x, w0, b.x * w1);
            acc[2 * j + 1] = fmaf(a.y, w0, b.y * w1);
        }
    }

    // Combine left/right corners (partner = lane ^ 4 holds same channels).
#pragma unroll
    for (int j = 0; j < 8; j++) {
        acc[j] += __shfl_xor_sync(0xffffffffu, acc[j], 4);
    }

    // Full-width store: lane l8 writes float4 of channels
    //   l8<4:  [8*l8 .. 8*l8+3]   (acc[0..3])
    //   l8>=4: [8*(l8-4)+4 .. +7] (acc[4..7])
    const int g = l8 & 3;
    const int hi = l8 >> 2;
    const float4 sv = hi ? make_float4(acc[4], acc[5], acc[6], acc[7])
                         : make_float4(acc[0], acc[1], acc[2], acc[3]);
    __stcs((float4*)(out + (size_t)pidx * DIM_FEAT + g * 8 + hi * 4), sv);
}

extern "C" void kernel_launch(void* const* d_in, const int* in_sizes, int n_in,
                              void* d_out, int out_size) {
    const float* coord = (const float*)d_in[0];   // [N, 2]
    const float* params = (const float*)d_in[1];  // [1, 32, 1024, 1024]
    float* out = (float*)d_out;                   // [N, 32]
    const int n = in_sizes[0] / 2;

    __half* pt;
    cudaGetSymbolAddress((void**)&pt, g_params_t);

    // 1) Transpose + fp32->fp16: [C,HW] -> [HW,C]
    dim3 tb(32, 8);
    transpose_kernel<<<HW / 32, tb>>>(params, pt);

    // 2) Sample: 8 lanes per point
    const int threads = 256;
    const long long total = (long long)n * 8;
    sample_kernel<<<(int)((total + threads - 1) / threads), threads>>>(
        (const float2*)coord, pt, out, n);
}

// round 6
// speedup vs baseline: 1.0893x; 1.0893x over previous
#include <cuda_runtime.h>
#include <cuda_fp16.h>
#include <cstdint>

#define GRID_H 1024
#define GRID_W 1024
#define DIM_FEAT 32
#define HW (GRID_H * GRID_W)

// 64 MB static scratch: params transposed to [H, W, C] fp16; fits L2 (126MB).
__device__ __half g_params_t[(size_t)DIM_FEAT * HW];

// ---------------------------------------------------------------------------
// Transpose [C, H*W] fp32 -> [H*W, C] fp16. Coalesced reads, half2 writes.
// ---------------------------------------------------------------------------
__global__ void transpose_kernel(const float* __restrict__ p,
                                 __half* __restrict__ pt) {
    __shared__ float tile[32][33];
    const int pix0 = blockIdx.x * 32;
    const int tx = threadIdx.x;
    const int ty = threadIdx.y;
    const int l = ty * 32 + tx;

#pragma unroll
    for (int i = 0; i < 32; i += 8) {
        tile[ty + i][tx] = __ldcs(&p[(size_t)(ty + i) * HW + pix0 + tx]);
    }
    __syncthreads();

    __half2* ptv = (__half2*)pt;
#pragma unroll
    for (int it = 0; it < 2; it++) {
        const int pix = it * 16 + (l >> 4);
        const int c2 = l & 15;
        const float a = tile[2 * c2 + 0][pix];
        const float b = tile[2 * c2 + 1][pix];
        ptv[(size_t)(pix0 + pix) * (DIM_FEAT / 2) + c2] =
            __floats2half2_rn(a, b);
    }
}

// Gather load with L2 evict-last policy: keep the param table L2-resident.
__device__ __forceinline__ uint4 ldg_el(const __half* p, uint64_t pol) {
    uint4 r;
    asm volatile("ld.global.nc.L2::cache_hint.v4.u32 {%0,%1,%2,%3}, [%4], %5;"
                 : "=r"(r.x), "=r"(r.y), "=r"(r.z), "=r"(r.w)
                 : "l"(p), "l"(pol));
    return r;
}

// ---------------------------------------------------------------------------
// Bilinear sample: 4 lanes per point, 2 points per thread (ILP=8 loads).
// Each lane handles 8 channels: 4 x 16B gathers per point, coalesced 64B per
// corner across the 4 lanes. Streaming stores keep the table in L2.
// ---------------------------------------------------------------------------
__global__ void sample_kernel(const float2* __restrict__ coord,
                              const __half* __restrict__ pt,
                              float* __restrict__ out, int n, int half) {
    const int t = blockIdx.x * blockDim.x + threadIdx.x;
    const int p0 = t >> 2;       // first point
    const int q = t & 3;         // channel octet (8 channels)
    if (p0 >= half) return;
    const int p1 = p0 + half;
    const bool has2 = (p1 < n);

    uint64_t pol;
    asm volatile("createpolicy.fractional.L2::evict_last.b64 %0, 1.0;"
                 : "=l"(pol));

    const float2 xy0 = __ldcs(&coord[p0]);
    const float2 xy1 = has2 ? __ldcs(&coord[p1]) : make_float2(0.f, 0.f);

    const int cq = 8 * q;

    // ---- address + weight computation for both points ----
    float w_[2][4];
    size_t b_[2][4];
#pragma unroll
    for (int s = 0; s < 2; s++) {
        const float2 xy = s ? xy1 : xy0;
        const float ix = (xy.x + 1.0f) * 0.5f * (float)(GRID_W - 1);
        const float iy = (xy.y + 1.0f) * 0.5f * (float)(GRID_H - 1);
        const float ix0f = floorf(ix);
        const float iy0f = floorf(iy);
        const float fx = ix - ix0f;
        const float fy = iy - iy0f;
        w_[s][0] = (1.0f - fx) * (1.0f - fy);
        w_[s][1] = fx * (1.0f - fy);
        w_[s][2] = (1.0f - fx) * fy;
        w_[s][3] = fx * fy;
        int ix0 = min(max((int)ix0f, 0), GRID_W - 1);
        int iy0 = min(max((int)iy0f, 0), GRID_H - 1);
        const int ix1 = min(ix0 + 1, GRID_W - 1);
        const int iy1 = min(iy0 + 1, GRID_H - 1);
        const size_t row0 = (size_t)iy0 * GRID_W;
        const size_t row1 = (size_t)iy1 * GRID_W;
        b_[s][0] = (row0 + ix0) * DIM_FEAT + cq;
        b_[s][1] = (row0 + ix1) * DIM_FEAT + cq;
        b_[s][2] = (row1 + ix0) * DIM_FEAT + cq;
        b_[s][3] = (row1 + ix1) * DIM_FEAT + cq;
    }

    // ---- issue all gathers (up to 8 in flight) ----
    uint4 v[2][4];
#pragma unroll
    for (int k = 0; k < 4; k++) v[0][k] = ldg_el(pt + b_[0][k], pol);
    if (has2) {
#pragma unroll
        for (int k = 0; k < 4; k++) v[1][k] = ldg_el(pt + b_[1][k], pol);
    }

    // ---- accumulate + store per point ----
#pragma unroll
    for (int s = 0; s < 2; s++) {
        if (s && !has2) break;
        float acc[8];
#pragma unroll
        for (int i = 0; i < 8; i++) acc[i] = 0.0f;
#pragma unroll
        for (int k = 0; k < 4; k++) {
            const unsigned u[4] = {v[s][k].x, v[s][k].y, v[s][k].z, v[s][k].w};
            const float w = w_[s][k];
#pragma unroll
            for (int j = 0; j < 4; j++) {
                const float2 a = __half22float2(*(const __half2*)&u[j]);
                acc[2 * j + 0] = fmaf(a.x, w, acc[2 * j + 0]);
                acc[2 * j + 1] = fmaf(a.y, w, acc[2 * j + 1]);
            }
        }
        const int pp = s ? p1 : p0;
        float4* o = (float4*)(out + (size_t)pp * DIM_FEAT + cq);
        __stcs(o + 0, make_float4(acc[0], acc[1], acc[2], acc[3]));
        __stcs(o + 1, make_float4(acc[4], acc[5], acc[6], acc[7]));
    }
}

extern "C" void kernel_launch(void* const* d_in, const int* in_sizes, int n_in,
                              void* d_out, int out_size) {
    const float* coord = (const float*)d_in[0];   // [N, 2]
    const float* params = (const float*)d_in[1];  // [1, 32, 1024, 1024]
    float* out = (float*)d_out;                   // [N, 32]
    const int n = in_sizes[0] / 2;
    const int half = (n + 1) / 2;

    __half* pt;
    cudaGetSymbolAddress((void**)&pt, g_params_t);

    dim3 tb(32, 8);
    transpose_kernel<<<HW / 32, tb>>>(params, pt);

    const int threads = 256;
    const long long total = (long long)half * 4;
    sample_kernel<<<(int)((total + threads - 1) / threads), threads>>>(
        (const float2*)coord, pt, out, n, half);
}

// round 7
// speedup vs baseline: 1.1232x; 1.0311x over previous
#include <cuda_runtime.h>
#include <cuda_fp16.h>
#include <cstdint>

#define GRID_H 1024
#define GRID_W 1024
#define DIM_FEAT 32
#define HW (GRID_H * GRID_W)

// 64 MB static scratch: params transposed to [H, W, C] fp16; fits L2 (126MB).
__device__ __half g_params_t[(size_t)DIM_FEAT * HW];

// ---------------------------------------------------------------------------
// Transpose [C, H*W] fp32 -> [H*W, C] fp16.
// Params read with evict-first (pure stream); table written with evict-last
// so it is L2-resident when the sample kernel starts (and across replays).
// ---------------------------------------------------------------------------
__global__ void transpose_kernel(const float* __restrict__ p,
                                 __half* __restrict__ pt) {
    __shared__ float tile[32][33];
    const int pix0 = blockIdx.x * 32;
    const int tx = threadIdx.x;
    const int ty = threadIdx.y;
    const int l = ty * 32 + tx;

    uint64_t pol;
    asm volatile("createpolicy.fractional.L2::evict_last.b64 %0, 1.0;"
                 : "=l"(pol));

#pragma unroll
    for (int i = 0; i < 32; i += 8) {
        tile[ty + i][tx] = __ldcs(&p[(size_t)(ty + i) * HW + pix0 + tx]);
    }
    __syncthreads();

    unsigned* ptv = (unsigned*)pt;
#pragma unroll
    for (int it = 0; it < 2; it++) {
        const int pix = it * 16 + (l >> 4);
        const int c2 = l & 15;
        const float a = tile[2 * c2 + 0][pix];
        const float b = tile[2 * c2 + 1][pix];
        const __half2 h = __floats2half2_rn(a, b);
        const unsigned hv = *(const unsigned*)&h;
        unsigned* dst = ptv + (size_t)(pix0 + pix) * (DIM_FEAT / 2) + c2;
        asm volatile("st.global.L2::cache_hint.u32 [%0], %1, %2;"
                     :: "l"(dst), "r"(hv), "l"(pol));
    }
}

// Gather load with L2 evict-last policy: keep the param table L2-resident.
__device__ __forceinline__ uint4 ldg_el(const __half* p, uint64_t pol) {
    uint4 r;
    asm volatile("ld.global.nc.L2::cache_hint.v4.u32 {%0,%1,%2,%3}, [%4], %5;"
                 : "=r"(r.x), "=r"(r.y), "=r"(r.z), "=r"(r.w)
                 : "l"(p), "l"(pol));
    return r;
}

// ---------------------------------------------------------------------------
// Bilinear sample: 4 lanes per point, each lane = 8 channels.
// 4 x 16B gathers per lane (64B coalesced per corner); streaming out stores.
// ---------------------------------------------------------------------------
__global__ void sample_kernel(const float2* __restrict__ coord,
                              const __half* __restrict__ pt,
                              float* __restrict__ out, int n) {
    const int t = blockIdx.x * blockDim.x + threadIdx.x;
    const int pidx = t >> 2;     // point index
    const int q = t & 3;         // channel octet (8 channels)
    if (pidx >= n) return;

    uint64_t pol;
    asm volatile("createpolicy.fractional.L2::evict_last.b64 %0, 1.0;"
                 : "=l"(pol));

    const float2 xy = __ldcs(&coord[pidx]);

    // align_corners=True mapping
    const float ix = (xy.x + 1.0f) * 0.5f * (float)(GRID_W - 1);
    const float iy = (xy.y + 1.0f) * 0.5f * (float)(GRID_H - 1);

    const float ix0f = floorf(ix);
    const float iy0f = floorf(iy);
    const float fx = ix - ix0f;
    const float fy = iy - iy0f;

    const float w_nw = (1.0f - fx) * (1.0f - fy);
    const float w_ne = fx * (1.0f - fy);
    const float w_sw = (1.0f - fx) * fy;
    const float w_se = fx * fy;

    int ix0 = min(max((int)ix0f, 0), GRID_W - 1);
    int iy0 = min(max((int)iy0f, 0), GRID_H - 1);
    const int ix1 = min(ix0 + 1, GRID_W - 1);
    const int iy1 = min(iy0 + 1, GRID_H - 1);

    const size_t row0 = (size_t)iy0 * GRID_W;
    const size_t row1 = (size_t)iy1 * GRID_W;
    const int cq = 8 * q;
    const uint4 r_nw = ldg_el(pt + (row0 + ix0) * DIM_FEAT + cq, pol);
    const uint4 r_ne = ldg_el(pt + (row0 + ix1) * DIM_FEAT + cq, pol);
    const uint4 r_sw = ldg_el(pt + (row1 + ix0) * DIM_FEAT + cq, pol);
    const uint4 r_se = ldg_el(pt + (row1 + ix1) * DIM_FEAT + cq, pol);

    float acc[8];
#pragma unroll
    for (int i = 0; i < 8; i++) acc[i] = 0.0f;

    auto accum = [&](const uint4& r, float w) {
        const unsigned u[4] = {r.x, r.y, r.z, r.w};
#pragma unroll
        for (int j = 0; j < 4; j++) {
            const float2 v = __half22float2(*(const __half2*)&u[j]);
            acc[2 * j + 0] = fmaf(v.x, w, acc[2 * j + 0]);
            acc[2 * j + 1] = fmaf(v.y, w, acc[2 * j + 1]);
        }
    };
    accum(r_nw, w_nw);
    accum(r_ne, w_ne);
    accum(r_sw, w_sw);
    accum(r_se, w_se);

    float4* o = (float4*)(out + (size_t)pidx * DIM_FEAT + cq);
    __stcs(o + 0, make_float4(acc[0], acc[1], acc[2], acc[3]));
    __stcs(o + 1, make_float4(acc[4], acc[5], acc[6], acc[7]));
}

extern "C" void kernel_launch(void* const* d_in, const int* in_sizes, int n_in,
                              void* d_out, int out_size) {
    const float* coord = (const float*)d_in[0];   // [N, 2]
    const float* params = (const float*)d_in[1];  // [1, 32, 1024, 1024]
    float* out = (float*)d_out;                   // [N, 32]
    const int n = in_sizes[0] / 2;

    __half* pt;
    cudaGetSymbolAddress((void**)&pt, g_params_t);

    dim3 tb(32, 8);
    transpose_kernel<<<HW / 32, tb>>>(params, pt);

    const int threads = 256;
    const long long total = (long long)n * 4;
    sample_kernel<<<(int)((total + threads - 1) / threads), threads>>>(
        (const float2*)coord, pt, out, n);
}